// round 8
// baseline (speedup 1.0000x reference)
#include <cuda_runtime.h>
#include <cuda_bf16.h>
#include <math.h>
#include <stdint.h>

#define BATCH 512
#define NNEG  2048
#define EDIM  256
#define K2    512

// CTA tile: BM (batch rows) x BN (neg cols), K chunk KT bf16 elems
#define BM 64
#define BN 128
#define KT 64              // 128 bytes per row
#define NCHUNK (K2 / KT)   // 8
#define NSTAGE 3

// smem per stage: Ahi(64x128B)=8K, Alo=8K, Bhi(128x128B)=16K, Blo=16K
#define OFF_AHI 0
#define OFF_ALO 8192
#define OFF_BHI 16384
#define OFF_BLO 32768
#define BUF_BYTES 49152
#define SMEM_TOTAL (NSTAGE * BUF_BYTES)   // 144 KB

// ---------------------------------------------------------------------------
// Scratch (__device__ globals; allocation-free rule)
// ---------------------------------------------------------------------------
__device__ __align__(16) __nv_bfloat16 g_Xhi[NNEG * K2];   // [n][k]  [t^2 | t] hi
__device__ __align__(16) __nv_bfloat16 g_Xlo[NNEG * K2];
__device__ __align__(16) __nv_bfloat16 g_Yhi[BATCH * K2];  // [b][k]  [rt^2 | -2*rt*a] hi
__device__ __align__(16) __nv_bfloat16 g_Ylo[BATCH * K2];
__device__ float g_c[BATCH];                               // ||a||^2

// ---------------------------------------------------------------------------
// helpers
// ---------------------------------------------------------------------------
#define SW128(o) ((o) ^ (((o) >> 3) & 0x70))

__device__ __forceinline__ uint32_t smem_u32(const void* p) {
    uint32_t a;
    asm("{ .reg .u64 t; cvta.to.shared.u64 t, %1; cvt.u32.u64 %0, t; }" : "=r"(a) : "l"(p));
    return a;
}
__device__ __forceinline__ void cpa(uint32_t dst, const void* src) {
    asm volatile("cp.async.cg.shared.global [%0], [%1], 16;" :: "r"(dst), "l"(src) : "memory");
}
__device__ __forceinline__ void ldsm_x4(uint32_t r[4], uint32_t addr) {
    asm volatile("ldmatrix.sync.aligned.m8n8.x4.shared.b16 {%0,%1,%2,%3}, [%4];"
        : "=r"(r[0]), "=r"(r[1]), "=r"(r[2]), "=r"(r[3]) : "r"(addr));
}
__device__ __forceinline__ void mma16816(float c[4], const uint32_t a[4],
                                         uint32_t b0, uint32_t b1) {
    asm volatile("mma.sync.aligned.m16n8k16.row.col.f32.bf16.bf16.f32 "
        "{%0,%1,%2,%3}, {%4,%5,%6,%7}, {%8,%9}, {%0,%1,%2,%3};"
        : "+f"(c[0]), "+f"(c[1]), "+f"(c[2]), "+f"(c[3])
        : "r"(a[0]), "r"(a[1]), "r"(a[2]), "r"(a[3]), "r"(b0), "r"(b1));
}

// pack 8 floats into 8 bf16 (uint4)
__device__ __forceinline__ uint4 pack8_hi(const float* v) {
    uint4 u;
    uint16_t* p = (uint16_t*)&u;
    #pragma unroll
    for (int i = 0; i < 8; i++) p[i] = __bfloat16_as_ushort(__float2bfloat16(v[i]));
    return u;
}
__device__ __forceinline__ uint4 pack8_lo(const float* v) {
    uint4 u;
    uint16_t* p = (uint16_t*)&u;
    #pragma unroll
    for (int i = 0; i < 8; i++) {
        __nv_bfloat16 h = __float2bfloat16(v[i]);
        p[i] = __bfloat16_as_ushort(__float2bfloat16(v[i] - __bfloat162float(h)));
    }
    return u;
}
__device__ __forceinline__ float warp_sum(float v) {
    #pragma unroll
    for (int o = 16; o > 0; o >>= 1) v += __shfl_xor_sync(0xffffffffu, v, o);
    return v;
}

// ---------------------------------------------------------------------------
// Merged prep: warp per row. Rows [0,BATCH) = head/rel; [BATCH, BATCH+NNEG) = tail.
// ---------------------------------------------------------------------------
__global__ __launch_bounds__(256) void prep_kernel(const float* __restrict__ head,
                                                   const float* __restrict__ tail,
                                                   const float* __restrict__ rel,
                                                   const int* __restrict__ rid32) {
    const int lane = threadIdx.x & 31;
    const int row  = blockIdx.x * 8 + (threadIdx.x >> 5);
    const int e0   = lane * 8;

    if (row < BATCH) {
        const int b = row;
        int probe = (lane < 8) ? rid32[2 * lane + 1] : 0;
        unsigned nz = __ballot_sync(0xffffffffu, probe != 0);
        const int stride = (nz == 0u) ? 2 : 1;

        float h[8];
        *(float4*)&h[0] = *(const float4*)&head[b * EDIM + e0];
        *(float4*)&h[4] = *(const float4*)&head[b * EDIM + e0 + 4];
        float s = 0.f;
        #pragma unroll
        for (int i = 0; i < 8; i++) s += h[i] * h[i];
        float inv = 1.0f / fmaxf(sqrtf(warp_sum(s)), 1e-12f);

        int r = rid32[b * stride];
        float rh[8], rt[8];
        *(float4*)&rh[0] = *(const float4*)&rel[(size_t)r * K2 + e0];
        *(float4*)&rh[4] = *(const float4*)&rel[(size_t)r * K2 + e0 + 4];
        *(float4*)&rt[0] = *(const float4*)&rel[(size_t)r * K2 + EDIM + e0];
        *(float4*)&rt[4] = *(const float4*)&rel[(size_t)r * K2 + EDIM + e0 + 4];

        float a[8], y1[8], y2[8];
        float s2 = 0.f;
        #pragma unroll
        for (int i = 0; i < 8; i++) {
            a[i]  = h[i] * inv * rh[i];
            y1[i] = rt[i] * rt[i];
            y2[i] = -2.0f * rt[i] * a[i];
            s2 += a[i] * a[i];
        }
        float c = warp_sum(s2);
        if (lane == 0) g_c[b] = c;

        *(uint4*)&g_Yhi[b * K2 + e0]        = pack8_hi(y1);
        *(uint4*)&g_Ylo[b * K2 + e0]        = pack8_lo(y1);
        *(uint4*)&g_Yhi[b * K2 + EDIM + e0] = pack8_hi(y2);
        *(uint4*)&g_Ylo[b * K2 + EDIM + e0] = pack8_lo(y2);
    } else {
        const int n = row - BATCH;
        float t[8];
        *(float4*)&t[0] = *(const float4*)&tail[n * EDIM + e0];
        *(float4*)&t[4] = *(const float4*)&tail[n * EDIM + e0 + 4];
        float s = 0.f;
        #pragma unroll
        for (int i = 0; i < 8; i++) s += t[i] * t[i];
        float inv = 1.0f / fmaxf(sqrtf(warp_sum(s)), 1e-12f);

        float tn[8], x1[8];
        #pragma unroll
        for (int i = 0; i < 8; i++) {
            tn[i] = t[i] * inv;
            x1[i] = tn[i] * tn[i];
        }
        *(uint4*)&g_Xhi[n * K2 + e0]        = pack8_hi(x1);
        *(uint4*)&g_Xlo[n * K2 + e0]        = pack8_lo(x1);
        *(uint4*)&g_Xhi[n * K2 + EDIM + e0] = pack8_hi(tn);
        *(uint4*)&g_Xlo[n * K2 + EDIM + e0] = pack8_lo(tn);
    }
}

// ---------------------------------------------------------------------------
// GEMM: out[b][n] = -sqrt(dot(Y[b],X[n]) + c[b]); mma.sync bf16, 3-term split
// 512 threads: 16 warps = 2 (m) x 8 (n), warp tile 32x16. 3-stage cp.async.
// ---------------------------------------------------------------------------
__device__ __forceinline__ void issue_chunk(uint32_t sb, int bufoff, int c,
                                            int tid, int bb, int bn) {
    // A (Y): 64 rows x 8 col16 = 512 slots, 1 hi + 1 lo per thread
    {
        int arow = tid >> 3;
        int col  = tid & 7;
        const __nv_bfloat16* yh = g_Yhi + (size_t)(bb * BM + arow) * K2 + c * KT + col * 8;
        const __nv_bfloat16* yl = g_Ylo + (size_t)(bb * BM + arow) * K2 + c * KT + col * 8;
        uint32_t off = SW128((uint32_t)(arow * 128 + col * 16));
        cpa(sb + bufoff + OFF_AHI + off, yh);
        cpa(sb + bufoff + OFF_ALO + off, yl);
    }
    // B (X): 128 rows x 8 col16 = 1024 slots, 2 hi + 2 lo per thread
    {
        int brow = tid >> 2;
        int bc   = (tid & 3) * 2;
        const __nv_bfloat16* xh = g_Xhi + (size_t)(bn * BN + brow) * K2 + c * KT;
        const __nv_bfloat16* xl = g_Xlo + (size_t)(bn * BN + brow) * K2 + c * KT;
        #pragma unroll
        for (int j = 0; j < 2; j++) {
            int col = bc + j;
            uint32_t off = SW128((uint32_t)(brow * 128 + col * 16));
            cpa(sb + bufoff + OFF_BHI + off, xh + col * 8);
            cpa(sb + bufoff + OFF_BLO + off, xl + col * 8);
        }
    }
    asm volatile("cp.async.commit_group;" ::: "memory");
}

// ldmatrix.x4 source address for a 16-row x 16-col(b16) tile at (row0, kb bytes)
__device__ __forceinline__ uint32_t tile_addr(uint32_t sb, int bufoff, int arroff,
                                              int row0, int kb, int lane) {
    int row = row0 + (lane & 15);
    int col = kb + ((lane >> 4) << 4);
    return sb + bufoff + arroff + SW128((uint32_t)(row * 128 + col));
}

__global__ __launch_bounds__(512, 1) void gemm_mma_kernel(float* __restrict__ out) {
    extern __shared__ char smem[];
    const uint32_t sb = smem_u32(smem);
    const int tid  = threadIdx.x;
    const int lane = tid & 31;
    const int wid  = tid >> 5;
    const int warp_m = wid & 1;    // 2 M-blocks of 32 (batch)
    const int warp_n = wid >> 1;   // 8 N-blocks of 16 (neg)
    const int wm0 = warp_m * 32;
    const int wn0 = warp_n * 16;
    const int bb = blockIdx.y;     // batch tile (0..7)
    const int bn = blockIdx.x;     // neg tile (0..15)

    float acc[2][2][4];
    #pragma unroll
    for (int mi = 0; mi < 2; mi++)
        #pragma unroll
        for (int nj = 0; nj < 2; nj++)
            #pragma unroll
            for (int q = 0; q < 4; q++) acc[mi][nj][q] = 0.f;

    issue_chunk(sb, 0, 0, tid, bb, bn);
    issue_chunk(sb, BUF_BYTES, 1, tid, bb, bn);

    for (int c = 0; c < NCHUNK; ++c) {
        const int bufoff = (c % NSTAGE) * BUF_BYTES;
        // all warps finished reading buffer (c+2)%NSTAGE at iter c-1
        if (c + 2 < NCHUNK) {
            issue_chunk(sb, ((c + 2) % NSTAGE) * BUF_BYTES, c + 2, tid, bb, bn);
            asm volatile("cp.async.wait_group 2;" ::: "memory");
        } else if (c + 2 == NCHUNK) {
            asm volatile("cp.async.wait_group 1;" ::: "memory");
        } else {
            asm volatile("cp.async.wait_group 0;" ::: "memory");
        }
        __syncthreads();

        #pragma unroll
        for (int kk = 0; kk < 4; kk++) {
            const int kb = kk * 32;
            uint32_t ah[2][4], al[2][4], bh[4], bl[4];
            #pragma unroll
            for (int mi = 0; mi < 2; mi++) {
                ldsm_x4(ah[mi], tile_addr(sb, bufoff, OFF_AHI, wm0 + mi * 16, kb, lane));
                ldsm_x4(al[mi], tile_addr(sb, bufoff, OFF_ALO, wm0 + mi * 16, kb, lane));
            }
            ldsm_x4(bh, tile_addr(sb, bufoff, OFF_BHI, wn0, kb, lane));
            ldsm_x4(bl, tile_addr(sb, bufoff, OFF_BLO, wn0, kb, lane));
            #pragma unroll
            for (int mi = 0; mi < 2; mi++) {
                #pragma unroll
                for (int nj = 0; nj < 2; nj++) {
                    mma16816(acc[mi][nj], ah[mi], bh[nj], bh[nj + 2]);
                    mma16816(acc[mi][nj], ah[mi], bl[nj], bl[nj + 2]);
                    mma16816(acc[mi][nj], al[mi], bh[nj], bh[nj + 2]);
                }
            }
        }
        __syncthreads();
    }

    // epilogue: D rows = batch, cols = neg (contiguous) -> float2 stores
    #pragma unroll
    for (int mi = 0; mi < 2; mi++) {
        #pragma unroll
        for (int rp = 0; rp < 2; rp++) {
            const int b_g = bb * BM + wm0 + mi * 16 + (lane >> 2) + rp * 8;
            const float cb = g_c[b_g];
            #pragma unroll
            for (int nj = 0; nj < 2; nj++) {
                const int n_g = bn * BN + wn0 + nj * 8 + (lane & 3) * 2;
                float d0 = acc[mi][nj][rp * 2 + 0];
                float d1 = acc[mi][nj][rp * 2 + 1];
                float2 o;
                o.x = -sqrtf(fmaxf(d0 + cb, 0.f));
                o.y = -sqrtf(fmaxf(d1 + cb, 0.f));
                *(float2*)&out[(size_t)b_g * NNEG + n_g] = o;
            }
        }
    }
}

// ---------------------------------------------------------------------------
extern "C" void kernel_launch(void* const* d_in, const int* in_sizes, int n_in,
                              void* d_out, int out_size) {
    const float* head  = (const float*)d_in[0];   // (512, 256)
    const float* tail  = (const float*)d_in[1];   // (1, 2048, 256)
    const float* rel   = (const float*)d_in[2];   // (1000, 512)
    const int*   rid32 = (const int*)d_in[3];     // (512,) int32 or int64
    float* out = (float*)d_out;                   // (512, 2048)

    cudaFuncSetAttribute(gemm_mma_kernel,
                         cudaFuncAttributeMaxDynamicSharedMemorySize, SMEM_TOTAL);

    prep_kernel<<<(BATCH + NNEG) / 8, 256>>>(head, tail, rel, rid32);

    dim3 grid(NNEG / BN, BATCH / BM);   // (16, 8) = 128 CTAs
    gemm_mma_kernel<<<grid, 512, SMEM_TOTAL>>>(out);
}

// round 10
// speedup vs baseline: 1.3023x; 1.3023x over previous
#include <cuda_runtime.h>
#include <cuda_bf16.h>
#include <math.h>
#include <stdint.h>

#define BATCH 512
#define NNEG  2048
#define EDIM  256
#define K2    512

// CTA tile: BM (batch rows) x BN (neg cols), K chunk KT bf16 elems
#define BM 64
#define BN 64
#define KT 64              // 128 bytes per row
#define NCHUNK (K2 / KT)   // 8
#define NSTAGE 3

// smem per stage: Ahi(64x128B)=8K, Alo=8K, Bhi(64x128B)=8K, Blo=8K
#define OFF_AHI 0
#define OFF_ALO 8192
#define OFF_BHI 16384
#define OFF_BLO 24576
#define BUF_BYTES 32768
#define SMEM_TOTAL (NSTAGE * BUF_BYTES)   // 96 KB -> 2 CTAs/SM

// ---------------------------------------------------------------------------
// Scratch (__device__ globals; allocation-free rule)
// ---------------------------------------------------------------------------
__device__ __align__(16) __nv_bfloat16 g_Xhi[NNEG * K2];   // [n][k]  [t^2 | t] hi
__device__ __align__(16) __nv_bfloat16 g_Xlo[NNEG * K2];
__device__ __align__(16) __nv_bfloat16 g_Yhi[BATCH * K2];  // [b][k]  [rt^2 | -2*rt*a] hi
__device__ __align__(16) __nv_bfloat16 g_Ylo[BATCH * K2];
__device__ float g_c[BATCH];                               // ||a||^2

// ---------------------------------------------------------------------------
// helpers
// ---------------------------------------------------------------------------
#define SW128(o) ((o) ^ (((o) >> 3) & 0x70))

__device__ __forceinline__ uint32_t smem_u32(const void* p) {
    uint32_t a;
    asm("{ .reg .u64 t; cvta.to.shared.u64 t, %1; cvt.u32.u64 %0, t; }" : "=r"(a) : "l"(p));
    return a;
}
__device__ __forceinline__ void cpa(uint32_t dst, const void* src) {
    asm volatile("cp.async.cg.shared.global [%0], [%1], 16;" :: "r"(dst), "l"(src) : "memory");
}
__device__ __forceinline__ void ldsm_x4(uint32_t r[4], uint32_t addr) {
    asm volatile("ldmatrix.sync.aligned.m8n8.x4.shared.b16 {%0,%1,%2,%3}, [%4];"
        : "=r"(r[0]), "=r"(r[1]), "=r"(r[2]), "=r"(r[3]) : "r"(addr));
}
__device__ __forceinline__ void mma16816(float c[4], const uint32_t a[4],
                                         uint32_t b0, uint32_t b1) {
    asm volatile("mma.sync.aligned.m16n8k16.row.col.f32.bf16.bf16.f32 "
        "{%0,%1,%2,%3}, {%4,%5,%6,%7}, {%8,%9}, {%0,%1,%2,%3};"
        : "+f"(c[0]), "+f"(c[1]), "+f"(c[2]), "+f"(c[3])
        : "r"(a[0]), "r"(a[1]), "r"(a[2]), "r"(a[3]), "r"(b0), "r"(b1));
}

// pack 8 floats into 8 bf16 (uint4)
__device__ __forceinline__ uint4 pack8_hi(const float* v) {
    uint4 u;
    uint16_t* p = (uint16_t*)&u;
    #pragma unroll
    for (int i = 0; i < 8; i++) p[i] = __bfloat16_as_ushort(__float2bfloat16(v[i]));
    return u;
}
__device__ __forceinline__ uint4 pack8_lo(const float* v) {
    uint4 u;
    uint16_t* p = (uint16_t*)&u;
    #pragma unroll
    for (int i = 0; i < 8; i++) {
        __nv_bfloat16 h = __float2bfloat16(v[i]);
        p[i] = __bfloat16_as_ushort(__float2bfloat16(v[i] - __bfloat162float(h)));
    }
    return u;
}
__device__ __forceinline__ float warp_sum(float v) {
    #pragma unroll
    for (int o = 16; o > 0; o >>= 1) v += __shfl_xor_sync(0xffffffffu, v, o);
    return v;
}

// ---------------------------------------------------------------------------
// Merged prep: warp per row. Rows [0,BATCH) = head/rel; [BATCH, BATCH+NNEG) = tail.
// ---------------------------------------------------------------------------
__global__ __launch_bounds__(256) void prep_kernel(const float* __restrict__ head,
                                                   const float* __restrict__ tail,
                                                   const float* __restrict__ rel,
                                                   const int* __restrict__ rid32) {
    const int lane = threadIdx.x & 31;
    const int row  = blockIdx.x * 8 + (threadIdx.x >> 5);
    const int e0   = lane * 8;

    if (row < BATCH) {
        const int b = row;
        int probe = (lane < 8) ? rid32[2 * lane + 1] : 0;
        unsigned nz = __ballot_sync(0xffffffffu, probe != 0);
        const int stride = (nz == 0u) ? 2 : 1;

        float h[8];
        *(float4*)&h[0] = *(const float4*)&head[b * EDIM + e0];
        *(float4*)&h[4] = *(const float4*)&head[b * EDIM + e0 + 4];
        float s = 0.f;
        #pragma unroll
        for (int i = 0; i < 8; i++) s += h[i] * h[i];
        float inv = 1.0f / fmaxf(sqrtf(warp_sum(s)), 1e-12f);

        int r = rid32[b * stride];
        float rh[8], rt[8];
        *(float4*)&rh[0] = *(const float4*)&rel[(size_t)r * K2 + e0];
        *(float4*)&rh[4] = *(const float4*)&rel[(size_t)r * K2 + e0 + 4];
        *(float4*)&rt[0] = *(const float4*)&rel[(size_t)r * K2 + EDIM + e0];
        *(float4*)&rt[4] = *(const float4*)&rel[(size_t)r * K2 + EDIM + e0 + 4];

        float a[8], y1[8], y2[8];
        float s2 = 0.f;
        #pragma unroll
        for (int i = 0; i < 8; i++) {
            a[i]  = h[i] * inv * rh[i];
            y1[i] = rt[i] * rt[i];
            y2[i] = -2.0f * rt[i] * a[i];
            s2 += a[i] * a[i];
        }
        float c = warp_sum(s2);
        if (lane == 0) g_c[b] = c;

        *(uint4*)&g_Yhi[b * K2 + e0]        = pack8_hi(y1);
        *(uint4*)&g_Ylo[b * K2 + e0]        = pack8_lo(y1);
        *(uint4*)&g_Yhi[b * K2 + EDIM + e0] = pack8_hi(y2);
        *(uint4*)&g_Ylo[b * K2 + EDIM + e0] = pack8_lo(y2);
    } else {
        const int n = row - BATCH;
        float t[8];
        *(float4*)&t[0] = *(const float4*)&tail[n * EDIM + e0];
        *(float4*)&t[4] = *(const float4*)&tail[n * EDIM + e0 + 4];
        float s = 0.f;
        #pragma unroll
        for (int i = 0; i < 8; i++) s += t[i] * t[i];
        float inv = 1.0f / fmaxf(sqrtf(warp_sum(s)), 1e-12f);

        float tn[8], x1[8];
        #pragma unroll
        for (int i = 0; i < 8; i++) {
            tn[i] = t[i] * inv;
            x1[i] = tn[i] * tn[i];
        }
        *(uint4*)&g_Xhi[n * K2 + e0]        = pack8_hi(x1);
        *(uint4*)&g_Xlo[n * K2 + e0]        = pack8_lo(x1);
        *(uint4*)&g_Xhi[n * K2 + EDIM + e0] = pack8_hi(tn);
        *(uint4*)&g_Xlo[n * K2 + EDIM + e0] = pack8_lo(tn);
    }
}

// ---------------------------------------------------------------------------
// GEMM: out[b][n] = -sqrt(dot(Y[b],X[n]) + c[b]); mma.sync bf16, 3-term split
// 128 threads: 4 warps = 2 (m) x 2 (n), warp tile 32x32. 3-stage cp.async.
// ---------------------------------------------------------------------------
__device__ __forceinline__ void issue_chunk(uint32_t sb, int bufoff, int c,
                                            int tid, int bb, int bn) {
    // A (Y): 64 rows x 8 col16 = 512 slots; each thread 4 hi + 4 lo
    {
        int arow = tid >> 1;
        int ac   = (tid & 1) * 4;
        const __nv_bfloat16* yh = g_Yhi + (size_t)(bb * BM + arow) * K2 + c * KT;
        const __nv_bfloat16* yl = g_Ylo + (size_t)(bb * BM + arow) * K2 + c * KT;
        #pragma unroll
        for (int j = 0; j < 4; j++) {
            int col = ac + j;
            uint32_t off = SW128((uint32_t)(arow * 128 + col * 16));
            cpa(sb + bufoff + OFF_AHI + off, yh + col * 8);
            cpa(sb + bufoff + OFF_ALO + off, yl + col * 8);
        }
    }
    // B (X): 64 rows x 8 col16 = 512 slots; each thread 4 hi + 4 lo
    {
        int brow = tid >> 1;
        int bc   = (tid & 1) * 4;
        const __nv_bfloat16* xh = g_Xhi + (size_t)(bn * BN + brow) * K2 + c * KT;
        const __nv_bfloat16* xl = g_Xlo + (size_t)(bn * BN + brow) * K2 + c * KT;
        #pragma unroll
        for (int j = 0; j < 4; j++) {
            int col = bc + j;
            uint32_t off = SW128((uint32_t)(brow * 128 + col * 16));
            cpa(sb + bufoff + OFF_BHI + off, xh + col * 8);
            cpa(sb + bufoff + OFF_BLO + off, xl + col * 8);
        }
    }
    asm volatile("cp.async.commit_group;" ::: "memory");
}

// ldmatrix.x4 source address for a 16-row x 16-col(b16) tile at (row0, kb bytes)
__device__ __forceinline__ uint32_t tile_addr(uint32_t sb, int bufoff, int arroff,
                                              int row0, int kb, int lane) {
    int row = row0 + (lane & 15);
    int col = kb + ((lane >> 4) << 4);
    return sb + bufoff + arroff + SW128((uint32_t)(row * 128 + col));
}

__global__ __launch_bounds__(128, 2) void gemm_mma_kernel(float* __restrict__ out) {
    extern __shared__ char smem[];
    const uint32_t sb = smem_u32(smem);
    const int tid  = threadIdx.x;
    const int lane = tid & 31;
    const int wid  = tid >> 5;
    const int warp_m = wid & 1;    // 2 M-blocks of 32 (batch)
    const int warp_n = wid >> 1;   // 2 N-blocks of 32 (neg)
    const int wm0 = warp_m * 32;
    const int wn0 = warp_n * 32;
    const int bb = blockIdx.y;     // batch tile (0..7)
    const int bn = blockIdx.x;     // neg tile (0..31)

    float acc[2][4][4];
    #pragma unroll
    for (int mi = 0; mi < 2; mi++)
        #pragma unroll
        for (int nj = 0; nj < 4; nj++)
            #pragma unroll
            for (int q = 0; q < 4; q++) acc[mi][nj][q] = 0.f;

    issue_chunk(sb, 0, 0, tid, bb, bn);
    issue_chunk(sb, BUF_BYTES, 1, tid, bb, bn);

    for (int c = 0; c < NCHUNK; ++c) {
        const int bufoff = (c % NSTAGE) * BUF_BYTES;
        if (c + 2 < NCHUNK) {
            issue_chunk(sb, ((c + 2) % NSTAGE) * BUF_BYTES, c + 2, tid, bb, bn);
            asm volatile("cp.async.wait_group 2;" ::: "memory");
        } else if (c + 2 == NCHUNK) {
            asm volatile("cp.async.wait_group 1;" ::: "memory");
        } else {
            asm volatile("cp.async.wait_group 0;" ::: "memory");
        }
        __syncthreads();

        #pragma unroll
        for (int kk = 0; kk < 4; kk++) {
            const int kb = kk * 32;
            uint32_t ah[2][4], al[2][4], bh[2][4], bl[2][4];
            #pragma unroll
            for (int mi = 0; mi < 2; mi++) {
                ldsm_x4(ah[mi], tile_addr(sb, bufoff, OFF_AHI, wm0 + mi * 16, kb, lane));
                ldsm_x4(al[mi], tile_addr(sb, bufoff, OFF_ALO, wm0 + mi * 16, kb, lane));
            }
            #pragma unroll
            for (int bi = 0; bi < 2; bi++) {
                ldsm_x4(bh[bi], tile_addr(sb, bufoff, OFF_BHI, wn0 + bi * 16, kb, lane));
                ldsm_x4(bl[bi], tile_addr(sb, bufoff, OFF_BLO, wn0 + bi * 16, kb, lane));
            }
            #pragma unroll
            for (int mi = 0; mi < 2; mi++) {
                #pragma unroll
                for (int nj = 0; nj < 4; nj++) {
                    const int bi = nj >> 1;
                    const int h  = nj & 1;
                    mma16816(acc[mi][nj], ah[mi], bh[bi][h], bh[bi][h + 2]);
                    mma16816(acc[mi][nj], ah[mi], bl[bi][h], bl[bi][h + 2]);
                    mma16816(acc[mi][nj], al[mi], bh[bi][h], bh[bi][h + 2]);
                }
            }
        }
        __syncthreads();
    }

    // epilogue: D rows = batch, cols = neg (contiguous) -> float2 stores
    #pragma unroll
    for (int mi = 0; mi < 2; mi++) {
        #pragma unroll
        for (int rp = 0; rp < 2; rp++) {
            const int b_g = bb * BM + wm0 + mi * 16 + (lane >> 2) + rp * 8;
            const float cb = g_c[b_g];
            #pragma unroll
            for (int nj = 0; nj < 4; nj++) {
                const int n_g = bn * BN + wn0 + nj * 8 + (lane & 3) * 2;
                float d0 = acc[mi][nj][rp * 2 + 0];
                float d1 = acc[mi][nj][rp * 2 + 1];
                float2 o;
                o.x = -sqrtf(fmaxf(d0 + cb, 0.f));
                o.y = -sqrtf(fmaxf(d1 + cb, 0.f));
                *(float2*)&out[(size_t)b_g * NNEG + n_g] = o;
            }
        }
    }
}

// ---------------------------------------------------------------------------
extern "C" void kernel_launch(void* const* d_in, const int* in_sizes, int n_in,
                              void* d_out, int out_size) {
    const float* head  = (const float*)d_in[0];   // (512, 256)
    const float* tail  = (const float*)d_in[1];   // (1, 2048, 256)
    const float* rel   = (const float*)d_in[2];   // (1000, 512)
    const int*   rid32 = (const int*)d_in[3];     // (512,) int32 or int64
    float* out = (float*)d_out;                   // (512, 2048)

    cudaFuncSetAttribute(gemm_mma_kernel,
                         cudaFuncAttributeMaxDynamicSharedMemorySize, SMEM_TOTAL);

    prep_kernel<<<(BATCH + NNEG) / 8, 256>>>(head, tail, rel, rid32);

    dim3 grid(NNEG / BN, BATCH / BM);   // (32, 8) = 256 CTAs
    gemm_mma_kernel<<<grid, 128, SMEM_TOTAL>>>(out);
}

// round 11
// speedup vs baseline: 1.4200x; 1.0904x over previous
#include <cuda_runtime.h>
#include <cuda_bf16.h>
#include <math.h>
#include <stdint.h>

#define BATCH 512
#define NNEG  2048
#define EDIM  256
#define K2    512

// CTA tile: BM (batch rows) x BN (neg cols), K chunk KT bf16 elems
#define BM 64
#define BN 128
#define KT 64          // 128 bytes per row
#define NCHUNK (K2 / KT)   // 8

// smem per buffer: Ahi(64x128B)=8K, Alo=8K, Bhi(128x128B)=16K, Blo=16K
#define OFF_AHI 0
#define OFF_ALO 8192
#define OFF_BHI 16384
#define OFF_BLO 32768
#define BUF_BYTES 49152
#define SMEM_TOTAL (2 * BUF_BYTES)   // 96 KB

// ---------------------------------------------------------------------------
// Scratch (__device__ globals; allocation-free rule)
// ---------------------------------------------------------------------------
__device__ __align__(16) __nv_bfloat16 g_Xhi[NNEG * K2];   // [n][k]  [t^2 | t] hi
__device__ __align__(16) __nv_bfloat16 g_Xlo[NNEG * K2];
__device__ __align__(16) __nv_bfloat16 g_Yhi[BATCH * K2];  // [b][k]  [rt^2 | -2*rt*a] hi
__device__ __align__(16) __nv_bfloat16 g_Ylo[BATCH * K2];
__device__ float g_c[BATCH];                               // ||a||^2

// ---------------------------------------------------------------------------
// helpers
// ---------------------------------------------------------------------------
#define SW128(o) ((o) ^ (((o) >> 3) & 0x70))

__device__ __forceinline__ uint32_t smem_u32(const void* p) {
    uint32_t a;
    asm("{ .reg .u64 t; cvta.to.shared.u64 t, %1; cvt.u32.u64 %0, t; }" : "=r"(a) : "l"(p));
    return a;
}
__device__ __forceinline__ void cpa(uint32_t dst, const void* src) {
    asm volatile("cp.async.cg.shared.global [%0], [%1], 16;" :: "r"(dst), "l"(src) : "memory");
}
__device__ __forceinline__ void ldsm_x4(uint32_t r[4], uint32_t addr) {
    asm volatile("ldmatrix.sync.aligned.m8n8.x4.shared.b16 {%0,%1,%2,%3}, [%4];"
        : "=r"(r[0]), "=r"(r[1]), "=r"(r[2]), "=r"(r[3]) : "r"(addr));
}
__device__ __forceinline__ void mma16816(float c[4], const uint32_t a[4],
                                         uint32_t b0, uint32_t b1) {
    asm volatile("mma.sync.aligned.m16n8k16.row.col.f32.bf16.bf16.f32 "
        "{%0,%1,%2,%3}, {%4,%5,%6,%7}, {%8,%9}, {%0,%1,%2,%3};"
        : "+f"(c[0]), "+f"(c[1]), "+f"(c[2]), "+f"(c[3])
        : "r"(a[0]), "r"(a[1]), "r"(a[2]), "r"(a[3]), "r"(b0), "r"(b1));
}

// pack 8 floats into 8 bf16 (uint4)
__device__ __forceinline__ uint4 pack8_hi(const float* v) {
    uint4 u;
    uint16_t* p = (uint16_t*)&u;
    #pragma unroll
    for (int i = 0; i < 8; i++) p[i] = __bfloat16_as_ushort(__float2bfloat16(v[i]));
    return u;
}
__device__ __forceinline__ uint4 pack8_lo(const float* v) {
    uint4 u;
    uint16_t* p = (uint16_t*)&u;
    #pragma unroll
    for (int i = 0; i < 8; i++) {
        __nv_bfloat16 h = __float2bfloat16(v[i]);
        p[i] = __bfloat16_as_ushort(__float2bfloat16(v[i] - __bfloat162float(h)));
    }
    return u;
}
__device__ __forceinline__ float warp_sum(float v) {
    #pragma unroll
    for (int o = 16; o > 0; o >>= 1) v += __shfl_xor_sync(0xffffffffu, v, o);
    return v;
}

// ---------------------------------------------------------------------------
// Merged prep: warp per row. Rows [0,BATCH) = head/rel; [BATCH, BATCH+NNEG) = tail.
// ---------------------------------------------------------------------------
__global__ __launch_bounds__(256) void prep_kernel(const float* __restrict__ head,
                                                   const float* __restrict__ tail,
                                                   const float* __restrict__ rel,
                                                   const int* __restrict__ rid32) {
    const int lane = threadIdx.x & 31;
    const int row  = blockIdx.x * 8 + (threadIdx.x >> 5);
    const int e0   = lane * 8;

    if (row < BATCH) {
        const int b = row;
        int probe = (lane < 8) ? rid32[2 * lane + 1] : 0;
        unsigned nz = __ballot_sync(0xffffffffu, probe != 0);
        const int stride = (nz == 0u) ? 2 : 1;

        float h[8];
        *(float4*)&h[0] = *(const float4*)&head[b * EDIM + e0];
        *(float4*)&h[4] = *(const float4*)&head[b * EDIM + e0 + 4];
        float s = 0.f;
        #pragma unroll
        for (int i = 0; i < 8; i++) s += h[i] * h[i];
        float inv = 1.0f / fmaxf(sqrtf(warp_sum(s)), 1e-12f);

        int r = rid32[b * stride];
        float rh[8], rt[8];
        *(float4*)&rh[0] = *(const float4*)&rel[(size_t)r * K2 + e0];
        *(float4*)&rh[4] = *(const float4*)&rel[(size_t)r * K2 + e0 + 4];
        *(float4*)&rt[0] = *(const float4*)&rel[(size_t)r * K2 + EDIM + e0];
        *(float4*)&rt[4] = *(const float4*)&rel[(size_t)r * K2 + EDIM + e0 + 4];

        float a[8], y1[8], y2[8];
        float s2 = 0.f;
        #pragma unroll
        for (int i = 0; i < 8; i++) {
            a[i]  = h[i] * inv * rh[i];
            y1[i] = rt[i] * rt[i];
            y2[i] = -2.0f * rt[i] * a[i];
            s2 += a[i] * a[i];
        }
        float c = warp_sum(s2);
        if (lane == 0) g_c[b] = c;

        *(uint4*)&g_Yhi[b * K2 + e0]        = pack8_hi(y1);
        *(uint4*)&g_Ylo[b * K2 + e0]        = pack8_lo(y1);
        *(uint4*)&g_Yhi[b * K2 + EDIM + e0] = pack8_hi(y2);
        *(uint4*)&g_Ylo[b * K2 + EDIM + e0] = pack8_lo(y2);
    } else {
        const int n = row - BATCH;
        float t[8];
        *(float4*)&t[0] = *(const float4*)&tail[n * EDIM + e0];
        *(float4*)&t[4] = *(const float4*)&tail[n * EDIM + e0 + 4];
        float s = 0.f;
        #pragma unroll
        for (int i = 0; i < 8; i++) s += t[i] * t[i];
        float inv = 1.0f / fmaxf(sqrtf(warp_sum(s)), 1e-12f);

        float tn[8], x1[8];
        #pragma unroll
        for (int i = 0; i < 8; i++) {
            tn[i] = t[i] * inv;
            x1[i] = tn[i] * tn[i];
        }
        *(uint4*)&g_Xhi[n * K2 + e0]        = pack8_hi(x1);
        *(uint4*)&g_Xlo[n * K2 + e0]        = pack8_lo(x1);
        *(uint4*)&g_Xhi[n * K2 + EDIM + e0] = pack8_hi(tn);
        *(uint4*)&g_Xlo[n * K2 + EDIM + e0] = pack8_lo(tn);
    }
}

// ---------------------------------------------------------------------------
// GEMM: out[b][n] = -sqrt(dot(Y[b],X[n]) + c[b]); mma.sync bf16, 3-term split
// 256 threads: 8 warps = 2 (m) x 4 (n), warp tile 32x32. 2-stage cp.async.
// MMA issue order: term-outermost so same-acc reuse distance = 8 (RAW hidden).
// ---------------------------------------------------------------------------
__device__ __forceinline__ void issue_chunk(uint32_t sb, int bufoff, int c,
                                            int tid, int bb, int bn) {
    // A (Y): 64 rows x 8 col16; thread -> row=tid>>2, cols 2*(tid&3)+{0,1}
    {
        int arow = tid >> 2;
        int ac = (tid & 3) * 2;
        const __nv_bfloat16* yh = g_Yhi + (size_t)(bb * BM + arow) * K2 + c * KT;
        const __nv_bfloat16* yl = g_Ylo + (size_t)(bb * BM + arow) * K2 + c * KT;
        #pragma unroll
        for (int j = 0; j < 2; j++) {
            int col = ac + j;
            uint32_t off = SW128((uint32_t)(arow * 128 + col * 16));
            cpa(sb + bufoff + OFF_AHI + off, yh + col * 8);
            cpa(sb + bufoff + OFF_ALO + off, yl + col * 8);
        }
    }
    // B (X): 128 rows x 8 col16; thread -> row=tid>>1, cols 4*(tid&1)+{0..3}
    {
        int brow = tid >> 1;
        int bc = (tid & 1) * 4;
        const __nv_bfloat16* xh = g_Xhi + (size_t)(bn * BN + brow) * K2 + c * KT;
        const __nv_bfloat16* xl = g_Xlo + (size_t)(bn * BN + brow) * K2 + c * KT;
        #pragma unroll
        for (int j = 0; j < 4; j++) {
            int col = bc + j;
            uint32_t off = SW128((uint32_t)(brow * 128 + col * 16));
            cpa(sb + bufoff + OFF_BHI + off, xh + col * 8);
            cpa(sb + bufoff + OFF_BLO + off, xl + col * 8);
        }
    }
    asm volatile("cp.async.commit_group;" ::: "memory");
}

// ldmatrix.x4 source address for a 16-row x 16-col(b16) tile at (row0, kb bytes)
__device__ __forceinline__ uint32_t tile_addr(uint32_t sb, int bufoff, int arroff,
                                              int row0, int kb, int lane) {
    int row = row0 + (lane & 15);
    int col = kb + ((lane >> 4) << 4);
    return sb + bufoff + arroff + SW128((uint32_t)(row * 128 + col));
}

__global__ __launch_bounds__(256, 1) void gemm_mma_kernel(float* __restrict__ out) {
    extern __shared__ char smem[];
    const uint32_t sb = smem_u32(smem);
    const int tid  = threadIdx.x;
    const int lane = tid & 31;
    const int wid  = tid >> 5;
    const int warp_m = wid & 1;    // 2 M-blocks of 32 (batch)
    const int warp_n = wid >> 1;   // 4 N-blocks of 32 (neg)
    const int wm0 = warp_m * 32;
    const int wn0 = warp_n * 32;
    const int bb = blockIdx.y;     // batch tile (0..7)
    const int bn = blockIdx.x;     // neg tile (0..15)

    float acc[2][4][4];
    #pragma unroll
    for (int mi = 0; mi < 2; mi++)
        #pragma unroll
        for (int nj = 0; nj < 4; nj++)
            #pragma unroll
            for (int q = 0; q < 4; q++) acc[mi][nj][q] = 0.f;

    issue_chunk(sb, 0, 0, tid, bb, bn);

    for (int c = 0; c < NCHUNK; ++c) {
        const int bufoff = (c & 1) * BUF_BYTES;
        if (c + 1 < NCHUNK) {
            issue_chunk(sb, ((c + 1) & 1) * BUF_BYTES, c + 1, tid, bb, bn);
            asm volatile("cp.async.wait_group 1;" ::: "memory");
        } else {
            asm volatile("cp.async.wait_group 0;" ::: "memory");
        }
        __syncthreads();

        #pragma unroll
        for (int kk = 0; kk < 4; kk++) {
            const int kb = kk * 32;
            uint32_t ah[2][4], al[2][4], bh[2][4], bl[2][4];
            #pragma unroll
            for (int mi = 0; mi < 2; mi++) {
                ldsm_x4(ah[mi], tile_addr(sb, bufoff, OFF_AHI, wm0 + mi * 16, kb, lane));
                ldsm_x4(al[mi], tile_addr(sb, bufoff, OFF_ALO, wm0 + mi * 16, kb, lane));
            }
            #pragma unroll
            for (int bi = 0; bi < 2; bi++) {
                ldsm_x4(bh[bi], tile_addr(sb, bufoff, OFF_BHI, wn0 + bi * 16, kb, lane));
                ldsm_x4(bl[bi], tile_addr(sb, bufoff, OFF_BLO, wn0 + bi * 16, kb, lane));
            }
            // term-outermost issue: 8 independent accs between same-acc reuses
            #pragma unroll
            for (int mi = 0; mi < 2; mi++)
                #pragma unroll
                for (int nj = 0; nj < 4; nj++)
                    mma16816(acc[mi][nj], ah[mi], bh[nj >> 1][nj & 1], bh[nj >> 1][(nj & 1) + 2]);
            #pragma unroll
            for (int mi = 0; mi < 2; mi++)
                #pragma unroll
                for (int nj = 0; nj < 4; nj++)
                    mma16816(acc[mi][nj], ah[mi], bl[nj >> 1][nj & 1], bl[nj >> 1][(nj & 1) + 2]);
            #pragma unroll
            for (int mi = 0; mi < 2; mi++)
                #pragma unroll
                for (int nj = 0; nj < 4; nj++)
                    mma16816(acc[mi][nj], al[mi], bh[nj >> 1][nj & 1], bh[nj >> 1][(nj & 1) + 2]);
        }
        __syncthreads();
    }

    // epilogue: D rows = batch, cols = neg (contiguous) -> float2 stores
    #pragma unroll
    for (int mi = 0; mi < 2; mi++) {
        #pragma unroll
        for (int rp = 0; rp < 2; rp++) {
            const int b_g = bb * BM + wm0 + mi * 16 + (lane >> 2) + rp * 8;
            const float cb = g_c[b_g];
            #pragma unroll
            for (int nj = 0; nj < 4; nj++) {
                const int n_g = bn * BN + wn0 + nj * 8 + (lane & 3) * 2;
                float d0 = acc[mi][nj][rp * 2 + 0];
                float d1 = acc[mi][nj][rp * 2 + 1];
                float2 o;
                o.x = -sqrtf(fmaxf(d0 + cb, 0.f));
                o.y = -sqrtf(fmaxf(d1 + cb, 0.f));
                *(float2*)&out[(size_t)b_g * NNEG + n_g] = o;
            }
        }
    }
}

// ---------------------------------------------------------------------------
extern "C" void kernel_launch(void* const* d_in, const int* in_sizes, int n_in,
                              void* d_out, int out_size) {
    const float* head  = (const float*)d_in[0];   // (512, 256)
    const float* tail  = (const float*)d_in[1];   // (1, 2048, 256)
    const float* rel   = (const float*)d_in[2];   // (1000, 512)
    const int*   rid32 = (const int*)d_in[3];     // (512,) int32 or int64
    float* out = (float*)d_out;                   // (512, 2048)

    cudaFuncSetAttribute(gemm_mma_kernel,
                         cudaFuncAttributeMaxDynamicSharedMemorySize, SMEM_TOTAL);

    prep_kernel<<<(BATCH + NNEG) / 8, 256>>>(head, tail, rel, rid32);

    dim3 grid(NNEG / BN, BATCH / BM);   // (16, 8) = 128 CTAs
    gemm_mma_kernel<<<grid, 256, SMEM_TOTAL>>>(out);
}

// round 12
// speedup vs baseline: 1.5588x; 1.0977x over previous
#include <cuda_runtime.h>
#include <cuda_bf16.h>
#include <math.h>
#include <stdint.h>

#define BATCH 512
#define NNEG  2048
#define EDIM  256
#define K2    512

// CTA tile: BM (batch rows) x BN (neg cols), K chunk KT bf16 elems
#define BM 64
#define BN 128
#define KT 64          // 128 bytes per row
#define NCHUNK (K2 / KT)   // 8

// smem per buffer: Ahi(64x128B)=8K, Alo=8K, Bhi(128x128B)=16K, Blo=16K
#define OFF_AHI 0
#define OFF_ALO 8192
#define OFF_BHI 16384
#define OFF_BLO 32768
#define BUF_BYTES 49152
#define SMEM_TOTAL (2 * BUF_BYTES)   // 96 KB

// ---------------------------------------------------------------------------
// Scratch (__device__ globals; allocation-free rule)
// ---------------------------------------------------------------------------
__device__ __align__(16) __nv_bfloat16 g_Xhi[NNEG * K2];   // [n][k]  [t^2 | t] hi
__device__ __align__(16) __nv_bfloat16 g_Xlo[NNEG * K2];
__device__ __align__(16) __nv_bfloat16 g_Yhi[BATCH * K2];  // [b][k]  [rt^2 | -2*rt*a] hi
__device__ __align__(16) __nv_bfloat16 g_Ylo[BATCH * K2];
__device__ float g_c[BATCH];                               // ||a||^2

// ---------------------------------------------------------------------------
// helpers
// ---------------------------------------------------------------------------
#define SW128(o) ((o) ^ (((o) >> 3) & 0x70))

__device__ __forceinline__ uint32_t smem_u32(const void* p) {
    uint32_t a;
    asm("{ .reg .u64 t; cvta.to.shared.u64 t, %1; cvt.u32.u64 %0, t; }" : "=r"(a) : "l"(p));
    return a;
}
__device__ __forceinline__ void cpa(uint32_t dst, const void* src) {
    asm volatile("cp.async.cg.shared.global [%0], [%1], 16;" :: "r"(dst), "l"(src) : "memory");
}
__device__ __forceinline__ void ldsm_x4(uint32_t r[4], uint32_t addr) {
    asm volatile("ldmatrix.sync.aligned.m8n8.x4.shared.b16 {%0,%1,%2,%3}, [%4];"
        : "=r"(r[0]), "=r"(r[1]), "=r"(r[2]), "=r"(r[3]) : "r"(addr));
}
__device__ __forceinline__ void mma16816(float c[4], const uint32_t a[4],
                                         uint32_t b0, uint32_t b1) {
    asm volatile("mma.sync.aligned.m16n8k16.row.col.f32.bf16.bf16.f32 "
        "{%0,%1,%2,%3}, {%4,%5,%6,%7}, {%8,%9}, {%0,%1,%2,%3};"
        : "+f"(c[0]), "+f"(c[1]), "+f"(c[2]), "+f"(c[3])
        : "r"(a[0]), "r"(a[1]), "r"(a[2]), "r"(a[3]), "r"(b0), "r"(b1));
}

// pack 8 floats into 8 bf16 (uint4)
__device__ __forceinline__ uint4 pack8_hi(const float* v) {
    uint4 u;
    uint16_t* p = (uint16_t*)&u;
    #pragma unroll
    for (int i = 0; i < 8; i++) p[i] = __bfloat16_as_ushort(__float2bfloat16(v[i]));
    return u;
}
__device__ __forceinline__ uint4 pack8_lo(const float* v) {
    uint4 u;
    uint16_t* p = (uint16_t*)&u;
    #pragma unroll
    for (int i = 0; i < 8; i++) {
        __nv_bfloat16 h = __float2bfloat16(v[i]);
        p[i] = __bfloat16_as_ushort(__float2bfloat16(v[i] - __bfloat162float(h)));
    }
    return u;
}
__device__ __forceinline__ float warp_sum(float v) {
    #pragma unroll
    for (int o = 16; o > 0; o >>= 1) v += __shfl_xor_sync(0xffffffffu, v, o);
    return v;
}

// ---------------------------------------------------------------------------
// Merged prep: warp per row. Rows [0,BATCH) = head/rel; [BATCH, BATCH+NNEG) = tail.
// ---------------------------------------------------------------------------
__global__ __launch_bounds__(256) void prep_kernel(const float* __restrict__ head,
                                                   const float* __restrict__ tail,
                                                   const float* __restrict__ rel,
                                                   const int* __restrict__ rid32) {
    const int lane = threadIdx.x & 31;
    const int row  = blockIdx.x * 8 + (threadIdx.x >> 5);
    const int e0   = lane * 8;

    if (row < BATCH) {
        const int b = row;
        int probe = (lane < 8) ? rid32[2 * lane + 1] : 0;
        unsigned nz = __ballot_sync(0xffffffffu, probe != 0);
        const int stride = (nz == 0u) ? 2 : 1;

        float h[8];
        *(float4*)&h[0] = *(const float4*)&head[b * EDIM + e0];
        *(float4*)&h[4] = *(const float4*)&head[b * EDIM + e0 + 4];
        float s = 0.f;
        #pragma unroll
        for (int i = 0; i < 8; i++) s += h[i] * h[i];
        float inv = 1.0f / fmaxf(sqrtf(warp_sum(s)), 1e-12f);

        int r = rid32[b * stride];
        float rh[8], rt[8];
        *(float4*)&rh[0] = *(const float4*)&rel[(size_t)r * K2 + e0];
        *(float4*)&rh[4] = *(const float4*)&rel[(size_t)r * K2 + e0 + 4];
        *(float4*)&rt[0] = *(const float4*)&rel[(size_t)r * K2 + EDIM + e0];
        *(float4*)&rt[4] = *(const float4*)&rel[(size_t)r * K2 + EDIM + e0 + 4];

        float a[8], y1[8], y2[8];
        float s2 = 0.f;
        #pragma unroll
        for (int i = 0; i < 8; i++) {
            a[i]  = h[i] * inv * rh[i];
            y1[i] = rt[i] * rt[i];
            y2[i] = -2.0f * rt[i] * a[i];
            s2 += a[i] * a[i];
        }
        float c = warp_sum(s2);
        if (lane == 0) g_c[b] = c;

        *(uint4*)&g_Yhi[b * K2 + e0]        = pack8_hi(y1);
        *(uint4*)&g_Ylo[b * K2 + e0]        = pack8_lo(y1);
        *(uint4*)&g_Yhi[b * K2 + EDIM + e0] = pack8_hi(y2);
        *(uint4*)&g_Ylo[b * K2 + EDIM + e0] = pack8_lo(y2);
    } else {
        const int n = row - BATCH;
        float t[8];
        *(float4*)&t[0] = *(const float4*)&tail[n * EDIM + e0];
        *(float4*)&t[4] = *(const float4*)&tail[n * EDIM + e0 + 4];
        float s = 0.f;
        #pragma unroll
        for (int i = 0; i < 8; i++) s += t[i] * t[i];
        float inv = 1.0f / fmaxf(sqrtf(warp_sum(s)), 1e-12f);

        float tn[8], x1[8];
        #pragma unroll
        for (int i = 0; i < 8; i++) {
            tn[i] = t[i] * inv;
            x1[i] = tn[i] * tn[i];
        }
        *(uint4*)&g_Xhi[n * K2 + e0]        = pack8_hi(x1);
        *(uint4*)&g_Xlo[n * K2 + e0]        = pack8_lo(x1);
        *(uint4*)&g_Xhi[n * K2 + EDIM + e0] = pack8_hi(tn);
        *(uint4*)&g_Xlo[n * K2 + EDIM + e0] = pack8_lo(tn);
    }
}

// ---------------------------------------------------------------------------
// GEMM: out[b][n] = -sqrt(dot(Y[b],X[n]) + c[b]); mma.sync bf16, 3-term split
// 512 threads / 16 warps. Warp tile 32x32 (2m x 4n layout as in R7).
// Intra-CTA split-K: warps 0-7 do kk={0,1}, warps 8-15 do kk={2,3};
// partials reduced through smem before the epilogue.
// ---------------------------------------------------------------------------
__device__ __forceinline__ void issue_chunk(uint32_t sb, int bufoff, int c,
                                            int tid, int bb, int bn) {
    // A (Y): 64 rows x 8 col16 = 512 slots; 1 hi + 1 lo per thread
    {
        int arow = tid >> 3;
        int col  = tid & 7;
        const __nv_bfloat16* yh = g_Yhi + (size_t)(bb * BM + arow) * K2 + c * KT + col * 8;
        const __nv_bfloat16* yl = g_Ylo + (size_t)(bb * BM + arow) * K2 + c * KT + col * 8;
        uint32_t off = SW128((uint32_t)(arow * 128 + col * 16));
        cpa(sb + bufoff + OFF_AHI + off, yh);
        cpa(sb + bufoff + OFF_ALO + off, yl);
    }
    // B (X): 128 rows x 8 col16 = 1024 slots; 2 hi + 2 lo per thread
    {
        int brow = tid >> 2;
        int bc   = (tid & 3) * 2;
        const __nv_bfloat16* xh = g_Xhi + (size_t)(bn * BN + brow) * K2 + c * KT;
        const __nv_bfloat16* xl = g_Xlo + (size_t)(bn * BN + brow) * K2 + c * KT;
        #pragma unroll
        for (int j = 0; j < 2; j++) {
            int col = bc + j;
            uint32_t off = SW128((uint32_t)(brow * 128 + col * 16));
            cpa(sb + bufoff + OFF_BHI + off, xh + col * 8);
            cpa(sb + bufoff + OFF_BLO + off, xl + col * 8);
        }
    }
    asm volatile("cp.async.commit_group;" ::: "memory");
}

// ldmatrix.x4 source address for a 16-row x 16-col(b16) tile at (row0, kb bytes)
__device__ __forceinline__ uint32_t tile_addr(uint32_t sb, int bufoff, int arroff,
                                              int row0, int kb, int lane) {
    int row = row0 + (lane & 15);
    int col = kb + ((lane >> 4) << 4);
    return sb + bufoff + arroff + SW128((uint32_t)(row * 128 + col));
}

__global__ __launch_bounds__(512, 1) void gemm_mma_kernel(float* __restrict__ out) {
    extern __shared__ char smem[];
    const uint32_t sb = smem_u32(smem);
    const int tid  = threadIdx.x;
    const int lane = tid & 31;
    const int wid  = tid >> 5;
    const int kh   = wid >> 3;      // k-half: 0 -> kk{0,1}, 1 -> kk{2,3}
    const int wsub = wid & 7;       // tile-warp id (same layout as R7)
    const int warp_m = wsub & 1;    // 2 M-blocks of 32 (batch)
    const int warp_n = wsub >> 1;   // 4 N-blocks of 32 (neg)
    const int wm0 = warp_m * 32;
    const int wn0 = warp_n * 32;
    const int bb = blockIdx.y;      // batch tile (0..7)
    const int bn = blockIdx.x;      // neg tile (0..15)

    float acc[2][4][4];
    #pragma unroll
    for (int mi = 0; mi < 2; mi++)
        #pragma unroll
        for (int nj = 0; nj < 4; nj++)
            #pragma unroll
            for (int q = 0; q < 4; q++) acc[mi][nj][q] = 0.f;

    issue_chunk(sb, 0, 0, tid, bb, bn);

    for (int c = 0; c < NCHUNK; ++c) {
        const int bufoff = (c & 1) * BUF_BYTES;
        if (c + 1 < NCHUNK) {
            issue_chunk(sb, ((c + 1) & 1) * BUF_BYTES, c + 1, tid, bb, bn);
            asm volatile("cp.async.wait_group 1;" ::: "memory");
        } else {
            asm volatile("cp.async.wait_group 0;" ::: "memory");
        }
        __syncthreads();

        #pragma unroll
        for (int kq = 0; kq < 2; kq++) {
            const int kb = (kh * 2 + kq) * 32;
            uint32_t ah[2][4], al[2][4], bh[2][4], bl[2][4];
            #pragma unroll
            for (int mi = 0; mi < 2; mi++) {
                ldsm_x4(ah[mi], tile_addr(sb, bufoff, OFF_AHI, wm0 + mi * 16, kb, lane));
                ldsm_x4(al[mi], tile_addr(sb, bufoff, OFF_ALO, wm0 + mi * 16, kb, lane));
            }
            #pragma unroll
            for (int bi = 0; bi < 2; bi++) {
                ldsm_x4(bh[bi], tile_addr(sb, bufoff, OFF_BHI, wn0 + bi * 16, kb, lane));
                ldsm_x4(bl[bi], tile_addr(sb, bufoff, OFF_BLO, wn0 + bi * 16, kb, lane));
            }
            #pragma unroll
            for (int mi = 0; mi < 2; mi++)
                #pragma unroll
                for (int nj = 0; nj < 4; nj++)
                    mma16816(acc[mi][nj], ah[mi], bh[nj >> 1][nj & 1], bh[nj >> 1][(nj & 1) + 2]);
            #pragma unroll
            for (int mi = 0; mi < 2; mi++)
                #pragma unroll
                for (int nj = 0; nj < 4; nj++)
                    mma16816(acc[mi][nj], ah[mi], bl[nj >> 1][nj & 1], bl[nj >> 1][(nj & 1) + 2]);
            #pragma unroll
            for (int mi = 0; mi < 2; mi++)
                #pragma unroll
                for (int nj = 0; nj < 4; nj++)
                    mma16816(acc[mi][nj], al[mi], bh[nj >> 1][nj & 1], bh[nj >> 1][(nj & 1) + 2]);
        }
        __syncthreads();
    }

    // ---- intra-CTA split-K reduction: kh=1 warps dump partials to smem ----
    // layout: [wsub][reg 0..31][lane] floats -> conflict-free STS.32/LDS.32
    if (kh == 1) {
        #pragma unroll
        for (int mi = 0; mi < 2; mi++)
            #pragma unroll
            for (int nj = 0; nj < 4; nj++)
                #pragma unroll
                for (int q = 0; q < 4; q++) {
                    int r = mi * 16 + nj * 4 + q;
                    *(float*)(smem + wsub * 4096 + r * 128 + lane * 4) = acc[mi][nj][q];
                }
    }
    __syncthreads();

    if (kh == 0) {
        #pragma unroll
        for (int mi = 0; mi < 2; mi++)
            #pragma unroll
            for (int nj = 0; nj < 4; nj++)
                #pragma unroll
                for (int q = 0; q < 4; q++) {
                    int r = mi * 16 + nj * 4 + q;
                    acc[mi][nj][q] += *(float*)(smem + wsub * 4096 + r * 128 + lane * 4);
                }

        // epilogue: D rows = batch, cols = neg (contiguous) -> float2 stores
        #pragma unroll
        for (int mi = 0; mi < 2; mi++) {
            #pragma unroll
            for (int rp = 0; rp < 2; rp++) {
                const int b_g = bb * BM + wm0 + mi * 16 + (lane >> 2) + rp * 8;
                const float cb = g_c[b_g];
                #pragma unroll
                for (int nj = 0; nj < 4; nj++) {
                    const int n_g = bn * BN + wn0 + nj * 8 + (lane & 3) * 2;
                    float d0 = acc[mi][nj][rp * 2 + 0];
                    float d1 = acc[mi][nj][rp * 2 + 1];
                    float2 o;
                    o.x = -sqrtf(fmaxf(d0 + cb, 0.f));
                    o.y = -sqrtf(fmaxf(d1 + cb, 0.f));
                    *(float2*)&out[(size_t)b_g * NNEG + n_g] = o;
                }
            }
        }
    }
}

// ---------------------------------------------------------------------------
extern "C" void kernel_launch(void* const* d_in, const int* in_sizes, int n_in,
                              void* d_out, int out_size) {
    const float* head  = (const float*)d_in[0];   // (512, 256)
    const float* tail  = (const float*)d_in[1];   // (1, 2048, 256)
    const float* rel   = (const float*)d_in[2];   // (1000, 512)
    const int*   rid32 = (const int*)d_in[3];     // (512,) int32 or int64
    float* out = (float*)d_out;                   // (512, 2048)

    cudaFuncSetAttribute(gemm_mma_kernel,
                         cudaFuncAttributeMaxDynamicSharedMemorySize, SMEM_TOTAL);

    prep_kernel<<<(BATCH + NNEG) / 8, 256>>>(head, tail, rel, rid32);

    dim3 grid(NNEG / BN, BATCH / BM);   // (16, 8) = 128 CTAs
    gemm_mma_kernel<<<grid, 512, SMEM_TOTAL>>>(out);
}